// round 14
// baseline (speedup 1.0000x reference)
#include <cuda_runtime.h>
#include <cuda_fp16.h>
#include <cstdint>
#include <math.h>

#define BSZ 4
#define C 128
#define NN 4096
#define G 8
#define CG 16   // C/G

// ---- scratch (device globals: allocation-free) ----
__device__ __half g_xnh[BSZ*NN*C];   // [b][n][c] fp16 (GN'd, transposed)
__device__ __half g_qh [BSZ*NN*C];   // [b][n][c] fp16 (pre-scaled by C^-0.5)
__device__ __half g_kh [BSZ*NN*C];   // [b][n][c] fp16
__device__ __half g_vth[BSZ*C*NN];   // [b][c][n] fp16 (V transposed)
__device__ __half g_oh [BSZ*NN*C];   // [b][n][c] fp16
__device__ __half g_wqh[3*C*C];      // qkv weight fp16
__device__ __half g_wph[C*C];        // proj weight fp16
__device__ float  g_ps [32][8];      // groupnorm partial sums
__device__ float  g_pss[32][8];      // groupnorm partial sumsq

// ============================================================
// helpers
// ============================================================
__device__ __forceinline__ uint32_t smem_u32(const void* p){
    uint32_t a;
    asm("{ .reg .u64 t; cvta.to.shared.u64 t, %1; cvt.u32.u64 %0, t; }" : "=r"(a) : "l"(p));
    return a;
}
__device__ __forceinline__ void mma16816(float* d, uint32_t a0, uint32_t a1,
                                         uint32_t a2, uint32_t a3,
                                         uint32_t b0, uint32_t b1){
    asm volatile("mma.sync.aligned.m16n8k16.row.col.f32.f16.f16.f32 "
        "{%0,%1,%2,%3}, {%4,%5,%6,%7}, {%8,%9}, {%0,%1,%2,%3};"
        : "+f"(d[0]), "+f"(d[1]), "+f"(d[2]), "+f"(d[3])
        : "r"(a0), "r"(a1), "r"(a2), "r"(a3), "r"(b0), "r"(b1));
}
__device__ __forceinline__ void ldm4(uint32_t* r, uint32_t addr){
    asm volatile("ldmatrix.sync.aligned.m8n8.x4.shared.b16 {%0,%1,%2,%3}, [%4];"
        : "=r"(r[0]), "=r"(r[1]), "=r"(r[2]), "=r"(r[3]) : "r"(addr));
}
__device__ __forceinline__ uint32_t h2u(__half2 h){ return *(uint32_t*)&h; }

#define CP16(dst, src) asm volatile("cp.async.cg.shared.global [%0], [%1], 16;" :: "r"(dst), "l"(src) : "memory")
#define CP_COMMIT()    asm volatile("cp.async.commit_group;" ::: "memory")
#define CP_WAIT1()     asm volatile("cp.async.wait_group 1;" ::: "memory")
#define CP_WAIT0()     asm volatile("cp.async.wait_group 0;" ::: "memory")

#define GP 272      // smem row pitch bytes (128 halfs + 8 pad)

// ============================================================
// GroupNorm partial stats (8 blocks per group) + weight conversion
// ============================================================
__global__ void gn_stats_w(const float* __restrict__ x,
                           const float* __restrict__ qw,
                           const float* __restrict__ pw) {
    int blk = blockIdx.x;
    if (blk >= 256) {                 // weight conversion: 96 blocks x 512
        int i = (blk - 256)*512 + threadIdx.x;
        g_wqh[i] = __float2half(qw[i]);
        if (i < C*C) g_wph[i] = __float2half(pw[i]);
        return;
    }
    int bg = blk >> 3, slot = blk & 7;
    const float4* p = (const float4*)(x + (size_t)bg*(CG*NN) + (size_t)slot*(CG*NN/8));
    float s = 0.f, ss = 0.f;
    #pragma unroll
    for (int i = threadIdx.x; i < 2048; i += 512) {
        float4 v = p[i];
        s  += v.x + v.y + v.z + v.w;
        ss += v.x*v.x + v.y*v.y + v.z*v.z + v.w*v.w;
    }
    __shared__ float sh_s[512], sh_ss[512];
    sh_s[threadIdx.x] = s; sh_ss[threadIdx.x] = ss;
    __syncthreads();
    for (int o = 256; o > 0; o >>= 1) {
        if (threadIdx.x < o) {
            sh_s[threadIdx.x]  += sh_s[threadIdx.x+o];
            sh_ss[threadIdx.x] += sh_ss[threadIdx.x+o];
        }
        __syncthreads();
    }
    if (threadIdx.x == 0) {
        g_ps [bg][slot] = sh_s[0];
        g_pss[bg][slot] = sh_ss[0];
    }
}

// ============================================================
// GN apply + transpose: x[b][c][n] fp32 -> g_xnh[b][n][c] fp16
// ============================================================
__global__ void __launch_bounds__(256) gn_xpose(const float* __restrict__ x,
                                                const float* __restrict__ gw,
                                                const float* __restrict__ gb) {
    __shared__ float tile[32][65];
    __shared__ float s_mean[2], s_rstd[2];
    int b = blockIdx.z, c0 = blockIdx.y*32, n0 = blockIdx.x*64;
    int tid = threadIdx.x;
    if (tid < 2) {
        int bg = b*G + (c0 >> 4) + tid;
        float s = 0.f, ss = 0.f;
        #pragma unroll
        for (int k = 0; k < 8; k++) { s += g_ps[bg][k]; ss += g_pss[bg][k]; }
        float inv = 1.f / (float)(CG*NN);
        float m = s*inv;
        float v = ss*inv - m*m;
        s_mean[tid] = m;
        s_rstd[tid] = rsqrtf(v + 1e-5f);
    }
    __syncthreads();
    #pragma unroll
    for (int i = tid; i < 2048; i += 256) {
        int r = i >> 6, col = i & 63;
        int c = c0 + r;
        int gsel = r >> 4;
        float sw = gw[c]*s_rstd[gsel];
        float sb = gb[c] - s_mean[gsel]*sw;
        float v = x[((size_t)(b*C + c))*NN + n0 + col];
        tile[r][col] = v*sw + sb;
    }
    __syncthreads();
    int n = tid >> 2, cp = tid & 3;
    __half hbuf[8];
    #pragma unroll
    for (int j = 0; j < 8; j++) hbuf[j] = __float2half(tile[cp*8 + j][n]);
    *(uint4*)(g_xnh + ((size_t)(b*NN + n0 + n))*C + c0 + cp*8) = *(uint4*)hbuf;
}

// ============================================================
// QKV GEMM fp16 mma: one CTA computes Q, K, V for its 128-row n-tile.
// smem: X [0,34816) | Wb0 [34816,69632) | Wb1 [69632,104448)
// ============================================================
__global__ void __launch_bounds__(256) qkv5(const float* __restrict__ bias) {
    extern __shared__ char sm[];
    const uint32_t smb = smem_u32(sm);
    int tid = threadIdx.x, lane = tid & 31, w = tid >> 5;
    int b = blockIdx.y, n0 = blockIdx.x*128;
    const __half* Xg = g_xnh + ((size_t)b*NN + n0)*C;

    #pragma unroll
    for (int i = tid; i < 2048; i += 256) {
        int r = i >> 4, c = i & 15;
        CP16(smb + r*GP + c*16, Xg + (size_t)r*C + c*8);
        CP16(smb + 34816 + r*GP + c*16, g_wqh + (size_t)r*C + c*8);
    }
    CP_COMMIT();
    #pragma unroll
    for (int i = tid; i < 2048; i += 256) {
        int r = i >> 4, c = i & 15;
        CP16(smb + 69632 + r*GP + c*16, g_wqh + (size_t)(C + r)*C + c*8);
    }
    CP_COMMIT();
    CP_WAIT1();
    __syncthreads();

    int q = lane & 3, rh = lane >> 2;
    int r0 = w*16 + rh;
    int lmat = lane >> 3, lrow = lane & 7;
    const uint32_t* ap0 = (const uint32_t*)(sm + r0*GP + q*4);
    const uint32_t* ap1 = (const uint32_t*)(sm + (r0+8)*GP + q*4);
    uint32_t qa[8][4];
    #pragma unroll
    for (int ks = 0; ks < 8; ks++) {
        qa[ks][0] = ap0[ks*8]; qa[ks][1] = ap1[ks*8];
        qa[ks][2] = ap0[ks*8+4]; qa[ks][3] = ap1[ks*8+4];
    }

    const float SC = 0.08838834764831845f;  // C^-0.5, folded into q
    int n_lo = n0 + r0, n_hi = n_lo + 8;

    #pragma unroll
    for (int os = 0; os < 3; os++) {
        uint32_t wb = smb + 34816 + (os & 1)*34816 + lrow*GP + lmat*16;
        float acc[16][4];
        #pragma unroll
        for (int nt = 0; nt < 16; nt++)
            #pragma unroll
            for (int j = 0; j < 4; j++) acc[nt][j] = 0.f;
        #pragma unroll
        for (int nt = 0; nt < 16; nt++)
            #pragma unroll
            for (int ks2 = 0; ks2 < 4; ks2++) {
                uint32_t bm[4];
                ldm4(bm, wb + nt*(8*GP) + ks2*64);
                mma16816(acc[nt], qa[2*ks2][0], qa[2*ks2][1], qa[2*ks2][2], qa[2*ks2][3], bm[0], bm[1]);
                mma16816(acc[nt], qa[2*ks2+1][0], qa[2*ks2+1][1], qa[2*ks2+1][2], qa[2*ks2+1][3], bm[2], bm[3]);
            }

        int o0 = os*128;
        #pragma unroll
        for (int nt = 0; nt < 16; nt++) {
            int o_loc = nt*8 + 2*q;
            float bv0 = bias[o0 + o_loc], bv1 = bias[o0 + o_loc + 1];
            float v0 = acc[nt][0] + bv0, v1 = acc[nt][1] + bv1;
            float v2 = acc[nt][2] + bv0, v3 = acc[nt][3] + bv1;
            if (os == 0) {
                v0 *= SC; v1 *= SC; v2 *= SC; v3 *= SC;
                __half* d = g_qh + (size_t)b*NN*C;
                *(__half2*)(d + (size_t)n_lo*C + o_loc) = __floats2half2_rn(v0, v1);
                *(__half2*)(d + (size_t)n_hi*C + o_loc) = __floats2half2_rn(v2, v3);
            } else if (os == 1) {
                __half* d = g_kh + (size_t)b*NN*C;
                *(__half2*)(d + (size_t)n_lo*C + o_loc) = __floats2half2_rn(v0, v1);
                *(__half2*)(d + (size_t)n_hi*C + o_loc) = __floats2half2_rn(v2, v3);
            } else {
                __half* d = g_vth + (size_t)b*C*NN;
                d[(size_t)(o_loc  )*NN + n_lo] = __float2half(v0);
                d[(size_t)(o_loc+1)*NN + n_lo] = __float2half(v1);
                d[(size_t)(o_loc  )*NN + n_hi] = __float2half(v2);
                d[(size_t)(o_loc+1)*NN + n_hi] = __float2half(v3);
            }
        }

        if (os == 0) {
            __syncthreads();
            #pragma unroll
            for (int i = tid; i < 2048; i += 256) {
                int r = i >> 4, c = i & 15;
                CP16(smb + 34816 + r*GP + c*16, g_wqh + (size_t)(2*C + r)*C + c*8);
            }
            CP_COMMIT();
            CP_WAIT1();
            __syncthreads();
        } else if (os == 1) {
            CP_WAIT0();
            __syncthreads();
        }
    }
}

// ============================================================
// Flash attention: 64 q / 8 warps (key-split) / 256 thr; 2 CTAs/SM.
// Warp w: rows (w&3)*16, keys (w>>2)*32 of each 64-key tile.
// Per-warp partial O accumulates across tiles; one epilogue reduction.
// smem: Q 64x272 [0,17408) | K 2x(64x272) [17408,52224) | V 2x(136x144) [52224,91392)
// ============================================================
#define SM_K 17408
#define KBUF 17408
#define SM_V 52224
#define VBUF 19584
#define VP   144
#define ATTN_SMEM 91392

__device__ __forceinline__ void ld_tile(uint32_t smb, const __half* Kg, const __half* Vt,
                                        int kt, int buf, int tid) {
    uint32_t sK = smb + SM_K + buf*KBUF;
    uint32_t sV = smb + SM_V + buf*VBUF;
    #pragma unroll
    for (int i = tid; i < 2048; i += 256) {
        if (i < 1024) {                      // K: 64 rows x 16 chunks
            int r = i >> 4, c = i & 15;
            CP16(sK + r*GP + c*16, Kg + (size_t)(kt+r)*C + c*8);
        } else {                             // V: 128 ch-rows x 8 chunks
            int j = i - 1024;
            int r = j >> 3, c = j & 7;
            CP16(sV + r*VP + c*16, Vt + (size_t)r*NN + kt + c*8);
        }
    }
}

__global__ void __launch_bounds__(256, 2) attn8() {
    extern __shared__ char sm[];
    const uint32_t smb = smem_u32(sm);
    int tid = threadIdx.x, lane = tid & 31, w = tid >> 5;   // w in 0..7
    int b = blockIdx.y, n0 = blockIdx.x * 64;
    int rw = w & 3;          // row group
    int kh = w >> 2;         // key half (0 or 1)

    const __half* Qg = g_qh  + ((size_t)b*NN + n0)*C;
    const __half* Kg = g_kh  + (size_t)b*NN*C;
    const __half* Vt = g_vth + (size_t)b*C*NN;

    // ones-channel rows 128..135 of both V buffers (row 128 = 1.0, rest 0)
    for (int i = tid; i < 576; i += 256) {
        int buf = i / 288, rem = i % 288;
        int rr = rem / 36, cw = rem % 36;
        *(uint32_t*)(sm + SM_V + buf*VBUF + (128+rr)*VP + cw*4) =
            (rr == 0) ? 0x3C003C00u : 0u;
    }
    // Q tile: 64 rows x 16 chunks
    #pragma unroll
    for (int i = tid; i < 1024; i += 256) {
        int r = i >> 4, c = i & 15;
        CP16(smb + r*GP + c*16, Qg + (size_t)r*C + c*8);
    }
    ld_tile(smb, Kg, Vt, 0, 0, tid);
    CP_COMMIT();
    ld_tile(smb, Kg, Vt, 64, 1, tid);
    CP_COMMIT();
    CP_WAIT1();
    __syncthreads();

    int q = lane & 3, rh = lane >> 2;
    int r0 = rw*16 + rh;
    int lmat = lane >> 3, lrow = lane & 7;

    // canonical A-fragment ldmatrix base for Q (rows rw*16..+15)
    uint32_t qfb = smb + (rw*16 + (lane & 15))*GP + (lane >> 4)*16;

    float oacc[17][4];
    #pragma unroll
    for (int nt = 0; nt < 17; nt++)
        #pragma unroll
        for (int j = 0; j < 4; j++) oacc[nt][j] = 0.f;

    for (int t = 0; t < 64; t++) {
        int buf = t & 1;
        uint32_t sK = smb + SM_K + buf*KBUF;
        uint32_t sV = smb + SM_V + buf*VBUF;

        // ---- S = Q K^T for this warp's 32 keys ----
        uint32_t kb = sK + (kh*32 + lrow)*GP + lmat*16;
        float sacc[4][4];
        #pragma unroll
        for (int nt = 0; nt < 4; nt++)
            #pragma unroll
            for (int j = 0; j < 4; j++) sacc[nt][j] = 0.f;
        #pragma unroll
        for (int ks2 = 0; ks2 < 4; ks2++) {
            uint32_t qa0[4], qa1[4];
            ldm4(qa0, qfb + ks2*64);
            ldm4(qa1, qfb + ks2*64 + 32);
            #pragma unroll
            for (int nt = 0; nt < 4; nt++) {
                uint32_t bm[4];
                ldm4(bm, kb + nt*(8*GP) + ks2*64);
                mma16816(sacc[nt], qa0[0], qa0[1], qa0[2], qa0[3], bm[0], bm[1]);
                mma16816(sacc[nt], qa1[0], qa1[1], qa1[2], qa1[3], bm[2], bm[3]);
            }
        }
        // ---- P = exp(S) in fp16 ----
        uint32_t ph[8];
        #pragma unroll
        for (int nt = 0; nt < 4; nt++) {
            ph[2*nt]   = h2u(h2exp(__floats2half2_rn(sacc[nt][0], sacc[nt][1])));
            ph[2*nt+1] = h2u(h2exp(__floats2half2_rn(sacc[nt][2], sacc[nt][3])));
        }
        // ---- O += P V over this warp's 32 keys (17th ntile = ones -> l) ----
        uint32_t vb = sV + lrow*VP + lmat*16 + kh*64;
        #pragma unroll
        for (int nt = 0; nt < 17; nt++) {
            uint32_t bm[4];
            ldm4(bm, vb + nt*(8*VP));
            mma16816(oacc[nt], ph[0], ph[1], ph[2], ph[3], bm[0], bm[1]);
            mma16816(oacc[nt], ph[4], ph[5], ph[6], ph[7], bm[2], bm[3]);
        }

        __syncthreads();
        if (t + 2 < 64) ld_tile(smb, Kg, Vt, (t+2)*64, buf, tid);
        CP_COMMIT();
        CP_WAIT1();
        __syncthreads();
    }

    // ---- epilogue: cross-warp key-half reduction in smem (fp32) ----
    __syncthreads();                 // everyone done with Q/K/V smem
    char* red = sm + rw*8704;        // 16 rows x 136 cols fp32, pitch 544
    if (kh == 1) {
        #pragma unroll
        for (int nt = 0; nt < 17; nt++) {
            *(float2*)(red + rh*544 + (nt*8 + 2*q)*4)     = make_float2(oacc[nt][0], oacc[nt][1]);
            *(float2*)(red + (rh+8)*544 + (nt*8 + 2*q)*4) = make_float2(oacc[nt][2], oacc[nt][3]);
        }
    }
    __syncthreads();
    if (kh == 0) {
        #pragma unroll
        for (int nt = 0; nt < 17; nt++) {
            float2 plo = *(float2*)(red + rh*544 + (nt*8 + 2*q)*4);
            float2 phi = *(float2*)(red + (rh+8)*544 + (nt*8 + 2*q)*4);
            oacc[nt][0] += plo.x; oacc[nt][1] += plo.y;
            oacc[nt][2] += phi.x; oacc[nt][3] += phi.y;
        }
        float l0 = __shfl_sync(0xffffffffu, oacc[16][0], lane & ~3);
        float l1 = __shfl_sync(0xffffffffu, oacc[16][2], lane & ~3);
        float inv0 = 1.f / l0, inv1 = 1.f / l1;
        __half* Og = g_oh + ((size_t)b*NN + n0)*C;
        #pragma unroll
        for (int nt = 0; nt < 16; nt++) {
            *(__half2*)(Og + (size_t)r0*C + nt*8 + 2*q) =
                __floats2half2_rn(oacc[nt][0]*inv0, oacc[nt][1]*inv0);
            *(__half2*)(Og + (size_t)(r0+8)*C + nt*8 + 2*q) =
                __floats2half2_rn(oacc[nt][2]*inv1, oacc[nt][3]*inv1);
        }
    }
}

// ============================================================
// Proj fp16 mma + bias + residual
// ============================================================
__global__ void __launch_bounds__(256) proj_h(const float* __restrict__ x,
                                              const float* __restrict__ pb,
                                              float* __restrict__ out) {
    extern __shared__ char sm[];
    const uint32_t smb = smem_u32(sm);
    int tid = threadIdx.x, lane = tid & 31, w = tid >> 5;
    int b = blockIdx.y, n0 = blockIdx.x*64;
    const __half* Og = g_oh + ((size_t)b*NN + n0)*C;
    #pragma unroll
    for (int i = tid; i < 2048; i += 256) {
        int r = i >> 4, c = i & 15;
        CP16(smb + r*GP + c*16, g_wph + (size_t)r*C + c*8);
        if (i < 1024) {
            int r2 = i >> 4, c2 = i & 15;
            CP16(smb + 34816 + r2*GP + c2*16, Og + (size_t)r2*C + c2*8);
        }
    }
    CP_COMMIT(); CP_WAIT0();
    __syncthreads();

    int q = lane & 3, rh = lane >> 2;
    int r0 = w*16 + rh;
    const uint32_t* ap0 = (const uint32_t*)(sm + r0*GP + q*4);
    const uint32_t* ap1 = (const uint32_t*)(sm + (r0+8)*GP + q*4);
    uint32_t qa[8][4];
    #pragma unroll
    for (int ks = 0; ks < 8; ks++) {
        qa[ks][0] = ap0[ks*8]; qa[ks][1] = ap1[ks*8];
        qa[ks][2] = ap0[ks*8+4]; qa[ks][3] = ap1[ks*8+4];
    }
    float acc[8][4];
    #pragma unroll
    for (int nt = 0; nt < 8; nt++)
        #pragma unroll
        for (int j = 0; j < 4; j++) acc[nt][j] = 0.f;

    int lmat = lane >> 3, lrow = lane & 7;
    uint32_t kb = smb + 34816 + lrow*GP + lmat*16;
    #pragma unroll
    for (int nt = 0; nt < 8; nt++)
        #pragma unroll
        for (int ks2 = 0; ks2 < 4; ks2++) {
            uint32_t bm[4];
            ldm4(bm, kb + nt*(8*GP) + ks2*64);
            mma16816(acc[nt], qa[2*ks2][0], qa[2*ks2][1], qa[2*ks2][2], qa[2*ks2][3], bm[0], bm[1]);
            mma16816(acc[nt], qa[2*ks2+1][0], qa[2*ks2+1][1], qa[2*ks2+1][2], qa[2*ks2+1][3], bm[2], bm[3]);
        }

    int c_lo = r0, c_hi = r0 + 8;
    float bvlo = pb[c_lo], bvhi = pb[c_hi];
    #pragma unroll
    for (int nt = 0; nt < 8; nt++) {
        int n = n0 + nt*8 + 2*q;
        size_t idx_lo = ((size_t)(b*C + c_lo))*NN + n;
        size_t idx_hi = ((size_t)(b*C + c_hi))*NN + n;
        float2 xv = *(const float2*)(x + idx_lo);
        *(float2*)(out + idx_lo) = make_float2(xv.x + acc[nt][0] + bvlo,
                                               xv.y + acc[nt][1] + bvlo);
        float2 xw = *(const float2*)(x + idx_hi);
        *(float2*)(out + idx_hi) = make_float2(xw.x + acc[nt][2] + bvhi,
                                               xw.y + acc[nt][3] + bvhi);
    }
}

// ============================================================
extern "C" void kernel_launch(void* const* d_in, const int* in_sizes, int n_in,
                              void* d_out, int out_size) {
    const float* x  = (const float*)d_in[0];
    const float* gw = (const float*)d_in[1];
    const float* gb = (const float*)d_in[2];
    const float* qw = (const float*)d_in[3];
    const float* qb = (const float*)d_in[4];
    const float* pw = (const float*)d_in[5];
    const float* pb = (const float*)d_in[6];
    float* out = (float*)d_out;

    gn_stats_w<<<352, 512>>>(x, qw, pw);
    gn_xpose<<<dim3(NN/64, C/32, BSZ), 256>>>(x, gw, gb);

    cudaFuncSetAttribute(qkv5, cudaFuncAttributeMaxDynamicSharedMemorySize, 104448);
    qkv5<<<dim3(NN/128, BSZ), 256, 104448>>>(qb);

    cudaFuncSetAttribute(attn8, cudaFuncAttributeMaxDynamicSharedMemorySize, ATTN_SMEM);
    attn8<<<dim3(NN/64, BSZ), 256, ATTN_SMEM>>>();

    cudaFuncSetAttribute(proj_h, cudaFuncAttributeMaxDynamicSharedMemorySize, 52224);
    proj_h<<<dim3(NN/64, BSZ), 256, 52224>>>(x, pb, out);
}

// round 16
// speedup vs baseline: 1.2720x; 1.2720x over previous
#include <cuda_runtime.h>
#include <cuda_fp16.h>
#include <cstdint>
#include <math.h>

#define BSZ 4
#define C 128
#define NN 4096
#define G 8
#define CG 16   // C/G

// ---- scratch (device globals: allocation-free) ----
__device__ __half g_xnh[BSZ*NN*C];   // [b][n][c] fp16 (GN'd, transposed)
__device__ __half g_qh [BSZ*NN*C];   // [b][n][c] fp16 (pre-scaled by C^-0.5)
__device__ __half g_kh [BSZ*NN*C];   // [b][n][c] fp16
__device__ __half g_vth[BSZ*C*NN];   // [b][c][n] fp16 (V transposed)
__device__ __half g_oh [BSZ*NN*C];   // [b][n][c] fp16
__device__ __half g_wqh[3*C*C];      // qkv weight fp16
__device__ __half g_wph[C*C];        // proj weight fp16
__device__ float  g_ps [32][8];      // groupnorm partial sums
__device__ float  g_pss[32][8];      // groupnorm partial sumsq

// ============================================================
// helpers
// ============================================================
__device__ __forceinline__ uint32_t smem_u32(const void* p){
    uint32_t a;
    asm("{ .reg .u64 t; cvta.to.shared.u64 t, %1; cvt.u32.u64 %0, t; }" : "=r"(a) : "l"(p));
    return a;
}
__device__ __forceinline__ void mma16816(float* d, uint32_t a0, uint32_t a1,
                                         uint32_t a2, uint32_t a3,
                                         uint32_t b0, uint32_t b1){
    asm volatile("mma.sync.aligned.m16n8k16.row.col.f32.f16.f16.f32 "
        "{%0,%1,%2,%3}, {%4,%5,%6,%7}, {%8,%9}, {%0,%1,%2,%3};"
        : "+f"(d[0]), "+f"(d[1]), "+f"(d[2]), "+f"(d[3])
        : "r"(a0), "r"(a1), "r"(a2), "r"(a3), "r"(b0), "r"(b1));
}
__device__ __forceinline__ void ldm4(uint32_t* r, uint32_t addr){
    asm volatile("ldmatrix.sync.aligned.m8n8.x4.shared.b16 {%0,%1,%2,%3}, [%4];"
        : "=r"(r[0]), "=r"(r[1]), "=r"(r[2]), "=r"(r[3]) : "r"(addr));
}
__device__ __forceinline__ uint32_t h2u(__half2 h){ return *(uint32_t*)&h; }
__device__ __forceinline__ __half2 u2h(uint32_t u){ return *(__half2*)&u; }

#define CP16(dst, src) asm volatile("cp.async.cg.shared.global [%0], [%1], 16;" :: "r"(dst), "l"(src) : "memory")
#define CP_COMMIT()    asm volatile("cp.async.commit_group;" ::: "memory")
#define CP_WAIT1()     asm volatile("cp.async.wait_group 1;" ::: "memory")
#define CP_WAIT0()     asm volatile("cp.async.wait_group 0;" ::: "memory")

#define GP 272      // smem row pitch bytes (128 halfs + 8 pad)

// ============================================================
// GroupNorm partial stats (8 blocks per group) + weight conversion
// ============================================================
__global__ void gn_stats_w(const float* __restrict__ x,
                           const float* __restrict__ qw,
                           const float* __restrict__ pw) {
    int blk = blockIdx.x;
    if (blk >= 256) {                 // weight conversion: 96 blocks x 512
        int i = (blk - 256)*512 + threadIdx.x;
        g_wqh[i] = __float2half(qw[i]);
        if (i < C*C) g_wph[i] = __float2half(pw[i]);
        return;
    }
    int bg = blk >> 3, slot = blk & 7;
    const float4* p = (const float4*)(x + (size_t)bg*(CG*NN) + (size_t)slot*(CG*NN/8));
    float s = 0.f, ss = 0.f;
    #pragma unroll
    for (int i = threadIdx.x; i < 2048; i += 512) {
        float4 v = p[i];
        s  += v.x + v.y + v.z + v.w;
        ss += v.x*v.x + v.y*v.y + v.z*v.z + v.w*v.w;
    }
    __shared__ float sh_s[512], sh_ss[512];
    sh_s[threadIdx.x] = s; sh_ss[threadIdx.x] = ss;
    __syncthreads();
    for (int o = 256; o > 0; o >>= 1) {
        if (threadIdx.x < o) {
            sh_s[threadIdx.x]  += sh_s[threadIdx.x+o];
            sh_ss[threadIdx.x] += sh_ss[threadIdx.x+o];
        }
        __syncthreads();
    }
    if (threadIdx.x == 0) {
        g_ps [bg][slot] = sh_s[0];
        g_pss[bg][slot] = sh_ss[0];
    }
}

// ============================================================
// GN apply + transpose: x[b][c][n] fp32 -> g_xnh[b][n][c] fp16
// ============================================================
__global__ void __launch_bounds__(256) gn_xpose(const float* __restrict__ x,
                                                const float* __restrict__ gw,
                                                const float* __restrict__ gb) {
    __shared__ float tile[32][65];
    __shared__ float s_mean[2], s_rstd[2];
    int b = blockIdx.z, c0 = blockIdx.y*32, n0 = blockIdx.x*64;
    int tid = threadIdx.x;
    if (tid < 2) {
        int bg = b*G + (c0 >> 4) + tid;
        float s = 0.f, ss = 0.f;
        #pragma unroll
        for (int k = 0; k < 8; k++) { s += g_ps[bg][k]; ss += g_pss[bg][k]; }
        float inv = 1.f / (float)(CG*NN);
        float m = s*inv;
        float v = ss*inv - m*m;
        s_mean[tid] = m;
        s_rstd[tid] = rsqrtf(v + 1e-5f);
    }
    __syncthreads();
    #pragma unroll
    for (int i = tid; i < 2048; i += 256) {
        int r = i >> 6, col = i & 63;
        int c = c0 + r;
        int gsel = r >> 4;
        float sw = gw[c]*s_rstd[gsel];
        float sb = gb[c] - s_mean[gsel]*sw;
        float v = x[((size_t)(b*C + c))*NN + n0 + col];
        tile[r][col] = v*sw + sb;
    }
    __syncthreads();
    int n = tid >> 2, cp = tid & 3;
    __half hbuf[8];
    #pragma unroll
    for (int j = 0; j < 8; j++) hbuf[j] = __float2half(tile[cp*8 + j][n]);
    *(uint4*)(g_xnh + ((size_t)(b*NN + n0 + n))*C + c0 + cp*8) = *(uint4*)hbuf;
}

// ============================================================
// QKV GEMM fp16 mma: one CTA computes Q, K, V for its 128-row n-tile.
// smem: X [0,34816) | Wb0 [34816,69632) | Wb1 [69632,104448)
// ============================================================
__global__ void __launch_bounds__(256) qkv5(const float* __restrict__ bias) {
    extern __shared__ char sm[];
    const uint32_t smb = smem_u32(sm);
    int tid = threadIdx.x, lane = tid & 31, w = tid >> 5;
    int b = blockIdx.y, n0 = blockIdx.x*128;
    const __half* Xg = g_xnh + ((size_t)b*NN + n0)*C;

    #pragma unroll
    for (int i = tid; i < 2048; i += 256) {
        int r = i >> 4, c = i & 15;
        CP16(smb + r*GP + c*16, Xg + (size_t)r*C + c*8);
        CP16(smb + 34816 + r*GP + c*16, g_wqh + (size_t)r*C + c*8);
    }
    CP_COMMIT();
    #pragma unroll
    for (int i = tid; i < 2048; i += 256) {
        int r = i >> 4, c = i & 15;
        CP16(smb + 69632 + r*GP + c*16, g_wqh + (size_t)(C + r)*C + c*8);
    }
    CP_COMMIT();
    CP_WAIT1();
    __syncthreads();

    int q = lane & 3, rh = lane >> 2;
    int r0 = w*16 + rh;
    int lmat = lane >> 3, lrow = lane & 7;
    const uint32_t* ap0 = (const uint32_t*)(sm + r0*GP + q*4);
    const uint32_t* ap1 = (const uint32_t*)(sm + (r0+8)*GP + q*4);
    uint32_t qa[8][4];
    #pragma unroll
    for (int ks = 0; ks < 8; ks++) {
        qa[ks][0] = ap0[ks*8]; qa[ks][1] = ap1[ks*8];
        qa[ks][2] = ap0[ks*8+4]; qa[ks][3] = ap1[ks*8+4];
    }

    const float SC = 0.08838834764831845f;  // C^-0.5, folded into q
    int n_lo = n0 + r0, n_hi = n_lo + 8;

    #pragma unroll
    for (int os = 0; os < 3; os++) {
        uint32_t wb = smb + 34816 + (os & 1)*34816 + lrow*GP + lmat*16;
        float acc[16][4];
        #pragma unroll
        for (int nt = 0; nt < 16; nt++)
            #pragma unroll
            for (int j = 0; j < 4; j++) acc[nt][j] = 0.f;
        #pragma unroll
        for (int nt = 0; nt < 16; nt++)
            #pragma unroll
            for (int ks2 = 0; ks2 < 4; ks2++) {
                uint32_t bm[4];
                ldm4(bm, wb + nt*(8*GP) + ks2*64);
                mma16816(acc[nt], qa[2*ks2][0], qa[2*ks2][1], qa[2*ks2][2], qa[2*ks2][3], bm[0], bm[1]);
                mma16816(acc[nt], qa[2*ks2+1][0], qa[2*ks2+1][1], qa[2*ks2+1][2], qa[2*ks2+1][3], bm[2], bm[3]);
            }

        int o0 = os*128;
        #pragma unroll
        for (int nt = 0; nt < 16; nt++) {
            int o_loc = nt*8 + 2*q;
            float bv0 = bias[o0 + o_loc], bv1 = bias[o0 + o_loc + 1];
            float v0 = acc[nt][0] + bv0, v1 = acc[nt][1] + bv1;
            float v2 = acc[nt][2] + bv0, v3 = acc[nt][3] + bv1;
            if (os == 0) {
                v0 *= SC; v1 *= SC; v2 *= SC; v3 *= SC;
                __half* d = g_qh + (size_t)b*NN*C;
                *(__half2*)(d + (size_t)n_lo*C + o_loc) = __floats2half2_rn(v0, v1);
                *(__half2*)(d + (size_t)n_hi*C + o_loc) = __floats2half2_rn(v2, v3);
            } else if (os == 1) {
                __half* d = g_kh + (size_t)b*NN*C;
                *(__half2*)(d + (size_t)n_lo*C + o_loc) = __floats2half2_rn(v0, v1);
                *(__half2*)(d + (size_t)n_hi*C + o_loc) = __floats2half2_rn(v2, v3);
            } else {
                __half* d = g_vth + (size_t)b*C*NN;
                d[(size_t)(o_loc  )*NN + n_lo] = __float2half(v0);
                d[(size_t)(o_loc+1)*NN + n_lo] = __float2half(v1);
                d[(size_t)(o_loc  )*NN + n_hi] = __float2half(v2);
                d[(size_t)(o_loc+1)*NN + n_hi] = __float2half(v3);
            }
        }

        if (os == 0) {
            __syncthreads();
            #pragma unroll
            for (int i = tid; i < 2048; i += 256) {
                int r = i >> 4, c = i & 15;
                CP16(smb + 34816 + r*GP + c*16, g_wqh + (size_t)(2*C + r)*C + c*8);
            }
            CP_COMMIT();
            CP_WAIT1();
            __syncthreads();
        } else if (os == 1) {
            CP_WAIT0();
            __syncthreads();
        }
    }
}

// ============================================================
// Flash attention attn9: 64 q / 4 warps / 128 thr; 2 CTAs/SM; grid 256.
// Warp (rw, kh): rows rw*32..+31 (TWO m16 row-tiles), keys kh*32..+31.
// K/V fragments reused across both row-tiles -> 48 ldm4 / 128 HMMA per tile.
// l via fp16 tile-sums accumulated in fp32 (no ones-channel).
// Epilogue: 2-way key-half reduction through dead Q/K smem.
// smem: Q 64x272 [0,17408) | K 2x(64x272) [17408,52224) | V 2x(128x144) [52224,89088)
// ============================================================
#define SM_K 17408
#define KBUF 17408
#define SM_V 52224
#define VBUF 18432
#define VP   144
#define ATTN_SMEM 89088

__device__ __forceinline__ void ld_tile(uint32_t smb, const __half* Kg, const __half* Vt,
                                        int kt, int buf, int tid) {
    uint32_t sK = smb + SM_K + buf*KBUF;
    uint32_t sV = smb + SM_V + buf*VBUF;
    #pragma unroll
    for (int i = tid; i < 2048; i += 128) {
        if (i < 1024) {                      // K: 64 rows x 16 chunks
            int r = i >> 4, c = i & 15;
            CP16(sK + r*GP + c*16, Kg + (size_t)(kt+r)*C + c*8);
        } else {                             // V: 128 ch-rows x 8 chunks
            int j = i - 1024;
            int r = j >> 3, c = j & 7;
            CP16(sV + r*VP + c*16, Vt + (size_t)r*NN + kt + c*8);
        }
    }
}

__global__ void __launch_bounds__(128, 2) attn9() {
    extern __shared__ char sm[];
    const uint32_t smb = smem_u32(sm);
    int tid = threadIdx.x, lane = tid & 31, w = tid >> 5;   // w in 0..3
    int b = blockIdx.y, n0 = blockIdx.x * 64;
    int rw = w & 1;          // row group (rows rw*32..+31)
    int kh = w >> 1;         // key half (0 or 1)

    const __half* Qg = g_qh  + ((size_t)b*NN + n0)*C;
    const __half* Kg = g_kh  + (size_t)b*NN*C;
    const __half* Vt = g_vth + (size_t)b*C*NN;

    // Q tile: 64 rows x 16 chunks  (+ tile0)
    #pragma unroll
    for (int i = tid; i < 1024; i += 128) {
        int r = i >> 4, c = i & 15;
        CP16(smb + r*GP + c*16, Qg + (size_t)r*C + c*8);
    }
    ld_tile(smb, Kg, Vt, 0, 0, tid);
    CP_COMMIT();
    ld_tile(smb, Kg, Vt, 64, 1, tid);
    CP_COMMIT();
    CP_WAIT1();
    __syncthreads();

    int q = lane & 3, rh = lane >> 2;
    int lmat = lane >> 3, lrow = lane & 7;

    // Q A-fragment ldmatrix bases for the two row-tiles
    uint32_t qfb0 = smb + (rw*32 + (lane & 15))*GP + (lane >> 4)*16;
    uint32_t qfb1 = qfb0 + 16*GP;

    float oacc[2][16][4];
    #pragma unroll
    for (int rt = 0; rt < 2; rt++)
        #pragma unroll
        for (int nt = 0; nt < 16; nt++)
            #pragma unroll
            for (int j = 0; j < 4; j++) oacc[rt][nt][j] = 0.f;
    float l00 = 0.f, l01 = 0.f, l10 = 0.f, l11 = 0.f;

    for (int t = 0; t < 64; t++) {
        int buf = t & 1;
        uint32_t sK = smb + SM_K + buf*KBUF;
        uint32_t sV = smb + SM_V + buf*VBUF;

        // ---- S = Q K^T : 2 row-tiles x this warp's 32 keys ----
        uint32_t kb = sK + (kh*32 + lrow)*GP + lmat*16;
        float sacc[2][4][4];
        #pragma unroll
        for (int rt = 0; rt < 2; rt++)
            #pragma unroll
            for (int nt = 0; nt < 4; nt++)
                #pragma unroll
                for (int j = 0; j < 4; j++) sacc[rt][nt][j] = 0.f;
        #pragma unroll
        for (int ks2 = 0; ks2 < 4; ks2++) {
            uint32_t qa0a[4], qa0b[4], qa1a[4], qa1b[4];
            ldm4(qa0a, qfb0 + ks2*64);
            ldm4(qa0b, qfb0 + ks2*64 + 32);
            ldm4(qa1a, qfb1 + ks2*64);
            ldm4(qa1b, qfb1 + ks2*64 + 32);
            #pragma unroll
            for (int nt = 0; nt < 4; nt++) {
                uint32_t bm[4];
                ldm4(bm, kb + nt*(8*GP) + ks2*64);
                mma16816(sacc[0][nt], qa0a[0], qa0a[1], qa0a[2], qa0a[3], bm[0], bm[1]);
                mma16816(sacc[0][nt], qa0b[0], qa0b[1], qa0b[2], qa0b[3], bm[2], bm[3]);
                mma16816(sacc[1][nt], qa1a[0], qa1a[1], qa1a[2], qa1a[3], bm[0], bm[1]);
                mma16816(sacc[1][nt], qa1b[0], qa1b[1], qa1b[2], qa1b[3], bm[2], bm[3]);
            }
        }

        // ---- P = exp(S) fp16; l via half2 tile-sum -> fp32 accumulate ----
        uint32_t ph[2][8];
        #pragma unroll
        for (int rt = 0; rt < 2; rt++) {
            #pragma unroll
            for (int nt = 0; nt < 4; nt++) {
                ph[rt][2*nt]   = h2u(h2exp(__floats2half2_rn(sacc[rt][nt][0], sacc[rt][nt][1])));
                ph[rt][2*nt+1] = h2u(h2exp(__floats2half2_rn(sacc[rt][nt][2], sacc[rt][nt][3])));
            }
            __half2 se = __hadd2(__hadd2(u2h(ph[rt][0]), u2h(ph[rt][2])),
                                 __hadd2(u2h(ph[rt][4]), u2h(ph[rt][6])));
            __half2 so = __hadd2(__hadd2(u2h(ph[rt][1]), u2h(ph[rt][3])),
                                 __hadd2(u2h(ph[rt][5]), u2h(ph[rt][7])));
            float2 fe = __half22float2(se);
            float2 fo = __half22float2(so);
            if (rt == 0) { l00 += fe.x + fe.y; l01 += fo.x + fo.y; }
            else         { l10 += fe.x + fe.y; l11 += fo.x + fo.y; }
        }

        // ---- O += P V over this warp's 32 keys (V frag reused x4) ----
        uint32_t vb = sV + lrow*VP + lmat*16 + kh*64;
        #pragma unroll
        for (int nt = 0; nt < 16; nt++) {
            uint32_t bm[4];
            ldm4(bm, vb + nt*(8*VP));
            mma16816(oacc[0][nt], ph[0][0], ph[0][1], ph[0][2], ph[0][3], bm[0], bm[1]);
            mma16816(oacc[0][nt], ph[0][4], ph[0][5], ph[0][6], ph[0][7], bm[2], bm[3]);
            mma16816(oacc[1][nt], ph[1][0], ph[1][1], ph[1][2], ph[1][3], bm[0], bm[1]);
            mma16816(oacc[1][nt], ph[1][4], ph[1][5], ph[1][6], ph[1][7], bm[2], bm[3]);
        }

        __syncthreads();
        if (t + 2 < 64) ld_tile(smb, Kg, Vt, (t+2)*64, buf, tid);
        CP_COMMIT();
        CP_WAIT1();
        __syncthreads();
    }

    // ---- epilogue: quad-reduce l, then 2-way key-half reduction in smem ----
    l00 += __shfl_xor_sync(0xffffffffu, l00, 1); l00 += __shfl_xor_sync(0xffffffffu, l00, 2);
    l01 += __shfl_xor_sync(0xffffffffu, l01, 1); l01 += __shfl_xor_sync(0xffffffffu, l01, 2);
    l10 += __shfl_xor_sync(0xffffffffu, l10, 1); l10 += __shfl_xor_sync(0xffffffffu, l10, 2);
    l11 += __shfl_xor_sync(0xffffffffu, l11, 1); l11 += __shfl_xor_sync(0xffffffffu, l11, 2);

    // red buffer: 32 rows x 136 fp32 cols (pitch 544) per rw, in dead Q/K smem
    char* red = sm + rw*17408;
    if (kh == 1) {
        #pragma unroll
        for (int rt = 0; rt < 2; rt++)
            #pragma unroll
            for (int nt = 0; nt < 16; nt++) {
                *(float2*)(red + (rt*16+rh)*544 + (nt*8+2*q)*4)   = make_float2(oacc[rt][nt][0], oacc[rt][nt][1]);
                *(float2*)(red + (rt*16+rh+8)*544 + (nt*8+2*q)*4) = make_float2(oacc[rt][nt][2], oacc[rt][nt][3]);
            }
        if (q == 0) {
            *(float*)(red + rh*544 + 512)      = l00;
            *(float*)(red + (rh+8)*544 + 512)  = l01;
            *(float*)(red + (16+rh)*544 + 512) = l10;
            *(float*)(red + (24+rh)*544 + 512) = l11;
        }
    }
    __syncthreads();
    if (kh == 0) {
        float lo00 = *(float*)(red + rh*544 + 512);
        float lo01 = *(float*)(red + (rh+8)*544 + 512);
        float lo10 = *(float*)(red + (16+rh)*544 + 512);
        float lo11 = *(float*)(red + (24+rh)*544 + 512);
        float inv00 = 1.f / (l00 + lo00), inv01 = 1.f / (l01 + lo01);
        float inv10 = 1.f / (l10 + lo10), inv11 = 1.f / (l11 + lo11);
        __half* Og = g_oh + ((size_t)b*NN + n0 + rw*32)*C;
        #pragma unroll
        for (int rt = 0; rt < 2; rt++) {
            float iv0 = rt ? inv10 : inv00;
            float iv1 = rt ? inv11 : inv01;
            #pragma unroll
            for (int nt = 0; nt < 16; nt++) {
                float2 plo = *(float2*)(red + (rt*16+rh)*544 + (nt*8+2*q)*4);
                float2 phi = *(float2*)(red + (rt*16+rh+8)*544 + (nt*8+2*q)*4);
                *(__half2*)(Og + (size_t)(rt*16+rh)*C + nt*8 + 2*q) =
                    __floats2half2_rn((oacc[rt][nt][0] + plo.x)*iv0, (oacc[rt][nt][1] + plo.y)*iv0);
                *(__half2*)(Og + (size_t)(rt*16+rh+8)*C + nt*8 + 2*q) =
                    __floats2half2_rn((oacc[rt][nt][2] + phi.x)*iv1, (oacc[rt][nt][3] + phi.y)*iv1);
            }
        }
    }
}

// ============================================================
// Proj fp16 mma + bias + residual
// ============================================================
__global__ void __launch_bounds__(256) proj_h(const float* __restrict__ x,
                                              const float* __restrict__ pb,
                                              float* __restrict__ out) {
    extern __shared__ char sm[];
    const uint32_t smb = smem_u32(sm);
    int tid = threadIdx.x, lane = tid & 31, w = tid >> 5;
    int b = blockIdx.y, n0 = blockIdx.x*64;
    const __half* Og = g_oh + ((size_t)b*NN + n0)*C;
    #pragma unroll
    for (int i = tid; i < 2048; i += 256) {
        int r = i >> 4, c = i & 15;
        CP16(smb + r*GP + c*16, g_wph + (size_t)r*C + c*8);
        if (i < 1024) {
            int r2 = i >> 4, c2 = i & 15;
            CP16(smb + 34816 + r2*GP + c2*16, Og + (size_t)r2*C + c2*8);
        }
    }
    CP_COMMIT(); CP_WAIT0();
    __syncthreads();

    int q = lane & 3, rh = lane >> 2;
    int r0 = w*16 + rh;
    const uint32_t* ap0 = (const uint32_t*)(sm + r0*GP + q*4);
    const uint32_t* ap1 = (const uint32_t*)(sm + (r0+8)*GP + q*4);
    uint32_t qa[8][4];
    #pragma unroll
    for (int ks = 0; ks < 8; ks++) {
        qa[ks][0] = ap0[ks*8]; qa[ks][1] = ap1[ks*8];
        qa[ks][2] = ap0[ks*8+4]; qa[ks][3] = ap1[ks*8+4];
    }
    float acc[8][4];
    #pragma unroll
    for (int nt = 0; nt < 8; nt++)
        #pragma unroll
        for (int j = 0; j < 4; j++) acc[nt][j] = 0.f;

    int lmat = lane >> 3, lrow = lane & 7;
    uint32_t kb = smb + 34816 + lrow*GP + lmat*16;
    #pragma unroll
    for (int nt = 0; nt < 8; nt++)
        #pragma unroll
        for (int ks2 = 0; ks2 < 4; ks2++) {
            uint32_t bm[4];
            ldm4(bm, kb + nt*(8*GP) + ks2*64);
            mma16816(acc[nt], qa[2*ks2][0], qa[2*ks2][1], qa[2*ks2][2], qa[2*ks2][3], bm[0], bm[1]);
            mma16816(acc[nt], qa[2*ks2+1][0], qa[2*ks2+1][1], qa[2*ks2+1][2], qa[2*ks2+1][3], bm[2], bm[3]);
        }

    int c_lo = r0, c_hi = r0 + 8;
    float bvlo = pb[c_lo], bvhi = pb[c_hi];
    #pragma unroll
    for (int nt = 0; nt < 8; nt++) {
        int n = n0 + nt*8 + 2*q;
        size_t idx_lo = ((size_t)(b*C + c_lo))*NN + n;
        size_t idx_hi = ((size_t)(b*C + c_hi))*NN + n;
        float2 xv = *(const float2*)(x + idx_lo);
        *(float2*)(out + idx_lo) = make_float2(xv.x + acc[nt][0] + bvlo,
                                               xv.y + acc[nt][1] + bvlo);
        float2 xw = *(const float2*)(x + idx_hi);
        *(float2*)(out + idx_hi) = make_float2(xw.x + acc[nt][2] + bvhi,
                                               xw.y + acc[nt][3] + bvhi);
    }
}

// ============================================================
extern "C" void kernel_launch(void* const* d_in, const int* in_sizes, int n_in,
                              void* d_out, int out_size) {
    const float* x  = (const float*)d_in[0];
    const float* gw = (const float*)d_in[1];
    const float* gb = (const float*)d_in[2];
    const float* qw = (const float*)d_in[3];
    const float* qb = (const float*)d_in[4];
    const float* pw = (const float*)d_in[5];
    const float* pb = (const float*)d_in[6];
    float* out = (float*)d_out;

    gn_stats_w<<<352, 512>>>(x, qw, pw);
    gn_xpose<<<dim3(NN/64, C/32, BSZ), 256>>>(x, gw, gb);

    cudaFuncSetAttribute(qkv5, cudaFuncAttributeMaxDynamicSharedMemorySize, 104448);
    qkv5<<<dim3(NN/128, BSZ), 256, 104448>>>(qb);

    cudaFuncSetAttribute(attn9, cudaFuncAttributeMaxDynamicSharedMemorySize, ATTN_SMEM);
    attn9<<<dim3(NN/64, BSZ), 128, ATTN_SMEM>>>();

    cudaFuncSetAttribute(proj_h, cudaFuncAttributeMaxDynamicSharedMemorySize, 52224);
    proj_h<<<dim3(NN/64, BSZ), 256, 52224>>>(x, pb, out);
}